// round 3
// baseline (speedup 1.0000x reference)
#include <cuda_runtime.h>
#include <mma.h>
#include <math.h>

using namespace nvcuda;

#define NE 8
#define NT 8192
#define NH 768
#define NI 3072

#define BM 128
#define BN 128
#define BK 32
#define THREADS 256
#define MAX_TILES 72
#define NTP (NT + NE * BM)   // padded sorted rows: 9216

// smem layout (dynamic): 2 stages of A(128x36) + B(32x132); Cs aliases
#define A_LD 36
#define B_LD 132
#define A_STAGE (BM * A_LD)          // 4608 floats
#define B_STAGE (BK * B_LD)          // 4224 floats
#define SMEM_FLOATS (2 * (A_STAGE + B_STAGE))
#define SMEM_BYTES (SMEM_FLOATS * 4) // 70656; Cs = 128*132*4 = 67584 fits

// ---------------- device scratch ----------------
__device__ int   g_counts[NE];
__device__ int   g_fill[NE];
__device__ int   g_offsets[NE + 1];
__device__ int   g_perm[NTP];
__device__ int   g_tile_e[MAX_TILES];
__device__ int   g_tile_row0[MAX_TILES];
__device__ int   g_ntiles;
__device__ float g_inter[(size_t)NTP * NI];  // 113 MB (sorted+padded)
__device__ float g_mid[(size_t)NT * NH];     // 24 MB (token order)

// ---------------- helpers ----------------
__device__ __forceinline__ void cp_async16(void* dst_smem, const void* src, int src_sz) {
    unsigned dst = (unsigned)__cvta_generic_to_shared(dst_smem);
    asm volatile("cp.async.cg.shared.global [%0], [%1], 16, %2;\n"
                 :: "r"(dst), "l"(src), "r"(src_sz));
}
__device__ __forceinline__ void cp_commit() { asm volatile("cp.async.commit_group;\n"); }
__device__ __forceinline__ void cp_wait1()  { asm volatile("cp.async.wait_group 1;\n"); }
__device__ __forceinline__ void cp_wait0()  { asm volatile("cp.async.wait_group 0;\n"); }

__device__ __forceinline__ float gelu_exact(float v) {
    return 0.5f * v * (1.0f + erff(v * 0.70710678118654752f));
}

// ---------------- sort-by-expert ----------------
__global__ void k_init() {
    int i = blockIdx.x * blockDim.x + threadIdx.x;
    if (i < NTP) g_perm[i] = -1;
    if (i < NE) { g_counts[i] = 0; g_fill[i] = 0; }
}
__global__ void k_count(const int* __restrict__ eid) {
    int t = blockIdx.x * blockDim.x + threadIdx.x;
    if (t < NT) atomicAdd(&g_counts[eid[t]], 1);
}
__global__ void k_build() {
    int off = 0, nt = 0;
    for (int e = 0; e < NE; e++) {
        g_offsets[e] = off;
        int c = g_counts[e];
        for (int r = 0; r < c; r += BM) {
            g_tile_e[nt] = e;
            g_tile_row0[nt] = off + r;
            nt++;
        }
        off += (c + BM - 1) & ~(BM - 1);   // align segments to BM
    }
    g_offsets[NE] = off;
    g_ntiles = nt;
}
__global__ void k_scatter(const int* __restrict__ eid) {
    int t = blockIdx.x * blockDim.x + threadIdx.x;
    if (t < NT) {
        int e = eid[t];
        g_perm[g_offsets[e] + atomicAdd(&g_fill[e], 1)] = t;
    }
}

// ---------------- shared GEMM core macro pieces ----------------
// warp layout: 8 warps as 4(m) x 2(n); warp tile 32 x 64; frags 2x4 of 16x16
struct Frags {
    wmma::fragment<wmma::accumulator, 16, 16, 8, float> acc[2][4];
};

__device__ __forceinline__ void compute_stage(const float* As, const float* Bs,
                                              int wm, int wn, Frags& F) {
#pragma unroll
    for (int kk = 0; kk < BK; kk += 8) {
        wmma::fragment<wmma::matrix_a, 16, 16, 8, wmma::precision::tf32, wmma::row_major> af[2];
        wmma::fragment<wmma::matrix_b, 16, 16, 8, wmma::precision::tf32, wmma::row_major> bf[4];
#pragma unroll
        for (int i = 0; i < 2; i++) {
            wmma::load_matrix_sync(af[i], As + (wm * 32 + i * 16) * A_LD + kk, A_LD);
#pragma unroll
            for (int u = 0; u < af[i].num_elements; u++)
                af[i].x[u] = wmma::__float_to_tf32(af[i].x[u]);
        }
#pragma unroll
        for (int j = 0; j < 4; j++) {
            wmma::load_matrix_sync(bf[j], Bs + kk * B_LD + wn * 64 + j * 16, B_LD);
#pragma unroll
            for (int u = 0; u < bf[j].num_elements; u++)
                bf[j].x[u] = wmma::__float_to_tf32(bf[j].x[u]);
        }
#pragma unroll
        for (int i = 0; i < 2; i++)
#pragma unroll
            for (int j = 0; j < 4; j++)
                wmma::mma_sync(F.acc[i][j], af[i], bf[j], F.acc[i][j]);
    }
}

// ---------------- GEMM1: g_inter = gelu(x[perm] @ W1[e] + b1[e]) ----------------
__global__ void __launch_bounds__(THREADS)
gemm1(const float* __restrict__ x, const float* __restrict__ w1,
      const float* __restrict__ b1) {
    int tile = blockIdx.y;
    if (tile >= g_ntiles) return;
    const int e    = g_tile_e[tile];
    const int row0 = g_tile_row0[tile];
    const int n0   = blockIdx.x * BN;
    const float* W = w1 + (size_t)e * NH * NI;   // ld = NI

    extern __shared__ float smem[];
    float* As = smem;                       // [2][A_STAGE]
    float* Bs = smem + 2 * A_STAGE;         // [2][B_STAGE]
    float* Cs = smem;                       // alias for epilogue
    __shared__ int Ptok[BM];

    const int tid = threadIdx.x;
    const int warp = tid >> 5;
    const int wm = warp >> 1, wn = warp & 1;

    if (tid < BM) Ptok[tid] = g_perm[row0 + tid];
    __syncthreads();

    Frags F;
#pragma unroll
    for (int i = 0; i < 2; i++)
#pragma unroll
        for (int j = 0; j < 4; j++) wmma::fill_fragment(F.acc[i][j], 0.0f);

    const int KT = NH / BK;   // 24

    // stage loader
    auto load_stage = [&](int s, int k0) {
        float* as = As + s * A_STAGE;
        float* bs = Bs + s * B_STAGE;
#pragma unroll
        for (int u = 0; u < 4; u++) {               // A: 1024 float4 / 256 thr
            int i = tid + u * THREADS;
            int r = i >> 3, c4 = (i & 7) * 4;
            int tok = Ptok[r];
            const float* src = (tok >= 0) ? x + (size_t)tok * NH + k0 + c4 : x;
            cp_async16(as + r * A_LD + c4, src, (tok >= 0) ? 16 : 0);
        }
#pragma unroll
        for (int u = 0; u < 4; u++) {               // B: 1024 float4
            int i = tid + u * THREADS;
            int r = i >> 5, c4 = (i & 31) * 4;
            cp_async16(bs + r * B_LD + c4, W + (size_t)(k0 + r) * NI + n0 + c4, 16);
        }
        cp_commit();
    };

    load_stage(0, 0);
    for (int kt = 0; kt < KT; kt++) {
        if (kt + 1 < KT) { load_stage((kt + 1) & 1, (kt + 1) * BK); cp_wait1(); }
        else             { cp_wait0(); }
        __syncthreads();
        int s = kt & 1;
        compute_stage(As + s * A_STAGE, Bs + s * B_STAGE, wm, wn, F);
        __syncthreads();
    }

    // epilogue via smem staging
#pragma unroll
    for (int i = 0; i < 2; i++)
#pragma unroll
        for (int j = 0; j < 4; j++)
            wmma::store_matrix_sync(Cs + (wm * 32 + i * 16) * B_LD + wn * 64 + j * 16,
                                    F.acc[i][j], B_LD, wmma::mem_row_major);
    __syncthreads();

    const float* bias = b1 + (size_t)e * NI + n0;
    for (int i4 = tid; i4 < BM * (BN / 4); i4 += THREADS) {
        int r = i4 >> 5, c4 = (i4 & 31) * 4;
        float4 v = *(const float4*)(Cs + r * B_LD + c4);
        v.x = gelu_exact(v.x + bias[c4 + 0]);
        v.y = gelu_exact(v.y + bias[c4 + 1]);
        v.z = gelu_exact(v.z + bias[c4 + 2]);
        v.w = gelu_exact(v.w + bias[c4 + 3]);
        *(float4*)(g_inter + (size_t)(row0 + r) * NI + n0 + c4) = v;
    }
}

// ---------------- GEMM2: g_mid[tok] = g_inter @ W2[e] + b2[e] + x[tok] ----------------
__global__ void __launch_bounds__(THREADS)
gemm2(const float* __restrict__ x, const float* __restrict__ w2,
      const float* __restrict__ b2) {
    int tile = blockIdx.y;
    if (tile >= g_ntiles) return;
    const int e    = g_tile_e[tile];
    const int row0 = g_tile_row0[tile];
    const int n0   = blockIdx.x * BN;
    const float* W = w2 + (size_t)e * NI * NH;   // ld = NH

    extern __shared__ float smem[];
    float* As = smem;
    float* Bs = smem + 2 * A_STAGE;
    float* Cs = smem;
    __shared__ int Ptok[BM];

    const int tid = threadIdx.x;
    const int warp = tid >> 5;
    const int wm = warp >> 1, wn = warp & 1;

    if (tid < BM) Ptok[tid] = g_perm[row0 + tid];
    __syncthreads();

    Frags F;
#pragma unroll
    for (int i = 0; i < 2; i++)
#pragma unroll
        for (int j = 0; j < 4; j++) wmma::fill_fragment(F.acc[i][j], 0.0f);

    const int KT = NI / BK;   // 96

    auto load_stage = [&](int s, int k0) {
        float* as = As + s * A_STAGE;
        float* bs = Bs + s * B_STAGE;
#pragma unroll
        for (int u = 0; u < 4; u++) {
            int i = tid + u * THREADS;
            int r = i >> 3, c4 = (i & 7) * 4;
            cp_async16(as + r * A_LD + c4,
                       g_inter + (size_t)(row0 + r) * NI + k0 + c4, 16);
        }
#pragma unroll
        for (int u = 0; u < 4; u++) {
            int i = tid + u * THREADS;
            int r = i >> 5, c4 = (i & 31) * 4;
            cp_async16(bs + r * B_LD + c4, W + (size_t)(k0 + r) * NH + n0 + c4, 16);
        }
        cp_commit();
    };

    load_stage(0, 0);
    for (int kt = 0; kt < KT; kt++) {
        if (kt + 1 < KT) { load_stage((kt + 1) & 1, (kt + 1) * BK); cp_wait1(); }
        else             { cp_wait0(); }
        __syncthreads();
        int s = kt & 1;
        compute_stage(As + s * A_STAGE, Bs + s * B_STAGE, wm, wn, F);
        __syncthreads();
    }

#pragma unroll
    for (int i = 0; i < 2; i++)
#pragma unroll
        for (int j = 0; j < 4; j++)
            wmma::store_matrix_sync(Cs + (wm * 32 + i * 16) * B_LD + wn * 64 + j * 16,
                                    F.acc[i][j], B_LD, wmma::mem_row_major);
    __syncthreads();

    const float* bias = b2 + (size_t)e * NH + n0;
    for (int i4 = tid; i4 < BM * (BN / 4); i4 += THREADS) {
        int r = i4 >> 5, c4 = (i4 & 31) * 4;
        int tok = Ptok[r];
        if (tok < 0) continue;
        float4 v = *(const float4*)(Cs + r * B_LD + c4);
        const float4 res = *(const float4*)(x + (size_t)tok * NH + n0 + c4);
        v.x += bias[c4 + 0] + res.x;
        v.y += bias[c4 + 1] + res.y;
        v.z += bias[c4 + 2] + res.z;
        v.w += bias[c4 + 3] + res.w;
        *(float4*)(g_mid + (size_t)tok * NH + n0 + c4) = v;
    }
}

// ---------------- LayerNorm ----------------
__global__ void ln_kernel(const float* __restrict__ gamma,
                          const float* __restrict__ beta,
                          float* __restrict__ out) {
    const int t = blockIdx.x;
    const float* v = g_mid + (size_t)t * NH;
    float* o = out + (size_t)t * NH;

    float s = 0.f, s2 = 0.f;
    for (int h = threadIdx.x; h < NH; h += blockDim.x) {
        float a = v[h];
        s += a; s2 += a * a;
    }
#pragma unroll
    for (int off = 16; off; off >>= 1) {
        s  += __shfl_down_sync(0xffffffffu, s, off);
        s2 += __shfl_down_sync(0xffffffffu, s2, off);
    }
    __shared__ float sh_s[8], sh_s2[8];
    int warp = threadIdx.x >> 5, lane = threadIdx.x & 31;
    if (lane == 0) { sh_s[warp] = s; sh_s2[warp] = s2; }
    __syncthreads();
    float S = 0.f, S2 = 0.f;
#pragma unroll
    for (int i = 0; i < 8; i++) { S += sh_s[i]; S2 += sh_s2[i]; }

    const float inv_h = 1.0f / (float)NH;
    float mean = S * inv_h;
    float var  = S2 * inv_h - mean * mean;
    float rstd = rsqrtf(var + 1e-12f);

    for (int h = threadIdx.x; h < NH; h += blockDim.x)
        o[h] = (v[h] - mean) * rstd * gamma[h] + beta[h];
}

// ---------------- launch ----------------
extern "C" void kernel_launch(void* const* d_in, const int* in_sizes, int n_in,
                              void* d_out, int out_size) {
    const float* x     = (const float*)d_in[0];
    const float* w1    = (const float*)d_in[1];
    const float* b1    = (const float*)d_in[2];
    const float* w2    = (const float*)d_in[3];
    const float* b2    = (const float*)d_in[4];
    const float* gamma = (const float*)d_in[5];
    const float* beta  = (const float*)d_in[6];
    const int*   eid   = (const int*)d_in[7];
    float* out = (float*)d_out;

    static bool attr_set = false;
    if (!attr_set) {
        cudaFuncSetAttribute(gemm1, cudaFuncAttributeMaxDynamicSharedMemorySize, SMEM_BYTES);
        cudaFuncSetAttribute(gemm2, cudaFuncAttributeMaxDynamicSharedMemorySize, SMEM_BYTES);
        attr_set = true;
    }

    k_init<<<(NTP + 255) / 256, 256>>>();
    k_count<<<NT / 256, 256>>>(eid);
    k_build<<<1, 1>>>();
    k_scatter<<<NT / 256, 256>>>(eid);

    gemm1<<<dim3(NI / BN, MAX_TILES), THREADS, SMEM_BYTES>>>(x, w1, b1);
    gemm2<<<dim3(NH / BN, MAX_TILES), THREADS, SMEM_BYTES>>>(x, w2, b2);
    ln_kernel<<<NT, 256>>>(gamma, beta, out);
}

// round 5
// speedup vs baseline: 1.2790x; 1.2790x over previous
#include <cuda_runtime.h>
#include <math.h>
#include <stdint.h>

#define NE 8
#define NT 8192
#define NH 768
#define NI 3072
#define BM 128
#define BN 128
#define BK 32
#define THREADS 256
#define MAX_TILES 72
#define NTP (NT + NE*BM)

#define A_LD 36
#define B_LD 132
#define A_STAGE (BM*A_LD)   // 4608 floats
#define B_STAGE (BK*B_LD)   // 4224 floats
#define SMEM_BYTES (2*(A_STAGE+B_STAGE)*4)   // 70656

__device__ int g_counts[NE];
__device__ int g_fill[NE];
__device__ int g_offsets[NE+1];
__device__ int g_perm[NTP];
__device__ int g_tile_e[MAX_TILES];
__device__ int g_tile_row0[MAX_TILES];
__device__ int g_ntiles;
__device__ float g_inter[(size_t)NTP*NI];
__device__ float g_mid[(size_t)NT*NH];

static __device__ __forceinline__ uint32_t f2tf32(float f){
    uint32_t r; asm("cvt.rna.tf32.f32 %0, %1;" : "=r"(r) : "f"(f)); return r;
}
static __device__ __forceinline__ float4 cvt4(float4 v){
    float4 o;
    o.x = __uint_as_float(f2tf32(v.x));
    o.y = __uint_as_float(f2tf32(v.y));
    o.z = __uint_as_float(f2tf32(v.z));
    o.w = __uint_as_float(f2tf32(v.w));
    return o;
}
static __device__ __forceinline__ void mma8(float* d, uint32_t a0, uint32_t a1,
                                            uint32_t a2, uint32_t a3,
                                            uint32_t b0, uint32_t b1){
    asm volatile("mma.sync.aligned.m16n8k8.row.col.f32.tf32.tf32.f32 "
        "{%0,%1,%2,%3},{%4,%5,%6,%7},{%8,%9},{%0,%1,%2,%3};"
        : "+f"(d[0]),"+f"(d[1]),"+f"(d[2]),"+f"(d[3])
        : "r"(a0),"r"(a1),"r"(a2),"r"(a3),"r"(b0),"r"(b1));
}
static __device__ __forceinline__ float gelu_exact(float v){
    return 0.5f*v*(1.0f+erff(v*0.70710678118654752f));
}

__global__ void k_init(){
    int i = blockIdx.x*blockDim.x + threadIdx.x;
    if (i < NTP) g_perm[i] = -1;
    if (i < NE) { g_counts[i]=0; g_fill[i]=0; }
}
__global__ void k_count(const int* __restrict__ eid){
    int t = blockIdx.x*blockDim.x + threadIdx.x;
    if (t < NT) atomicAdd(&g_counts[eid[t]], 1);
}
__global__ void k_build(){
    int off=0, nt=0;
    for (int e=0;e<NE;e++){
        g_offsets[e]=off; int c=g_counts[e];
        for (int r=0;r<c;r+=BM){ g_tile_e[nt]=e; g_tile_row0[nt]=off+r; nt++; }
        off += (c + BM-1) & ~(BM-1);
    }
    g_offsets[NE]=off; g_ntiles=nt;
}
__global__ void k_scatter(const int* __restrict__ eid){
    int t = blockIdx.x*blockDim.x + threadIdx.x;
    if (t < NT){ int e=eid[t]; g_perm[g_offsets[e]+atomicAdd(&g_fill[e],1)]=t; }
}

// compute one BK=32 stage: 4 k-slices, warp tile 32x64 (2 m-tiles x 8 n-tiles)
static __device__ __forceinline__ void compute_stage(const float* As, const float* Bs,
                                                     int wm, int wn, int gi, int tg,
                                                     float acc[2][8][4]){
    const float* aptr = As + (wm*32 + gi)*A_LD + tg;
    const float* bptr = Bs + tg*B_LD + wn*64 + gi;
#pragma unroll
    for (int kk=0; kk<BK; kk+=8){
        uint32_t a[2][4];
#pragma unroll
        for (int mt=0; mt<2; mt++){
            const float* p = aptr + mt*16*A_LD + kk;
            a[mt][0] = __float_as_uint(p[0]);
            a[mt][1] = __float_as_uint(p[8*A_LD]);
            a[mt][2] = __float_as_uint(p[4]);
            a[mt][3] = __float_as_uint(p[8*A_LD+4]);
        }
        uint32_t b[8][2];
#pragma unroll
        for (int nt=0; nt<8; nt++){
            b[nt][0] = __float_as_uint(bptr[kk*B_LD + nt*8]);
            b[nt][1] = __float_as_uint(bptr[(kk+4)*B_LD + nt*8]);
        }
#pragma unroll
        for (int mt=0; mt<2; mt++)
#pragma unroll
            for (int nt=0; nt<8; nt++)
                mma8(acc[mt][nt], a[mt][0],a[mt][1],a[mt][2],a[mt][3], b[nt][0],b[nt][1]);
    }
}

// ========================= GEMM1 =========================
__global__ void __launch_bounds__(THREADS)
gemm1(const float* __restrict__ x, const float* __restrict__ w1,
      const float* __restrict__ b1)
{
    int tile = blockIdx.y;
    if (tile >= g_ntiles) return;
    const int e = g_tile_e[tile], row0 = g_tile_row0[tile];
    const int n0 = blockIdx.x * BN;
    const float* W = w1 + (size_t)e*NH*NI;

    extern __shared__ float sm[];
    float* As = sm;                    // [2][A_STAGE]
    float* Bs = sm + 2*A_STAGE;        // [2][B_STAGE]
    __shared__ int Ptok[BM];
    __shared__ float sbias[BN];

    const int tid = threadIdx.x, w = tid>>5, l = tid&31;
    const int wm = w>>1, wn = w&1, gi = l>>2, tg = l&3;
    const int ar = tid>>1, ah = tid&1;     // A: row, 16-col half
    const int br = tid>>3, bq = tid&7;     // B: k-row, 16-col chunk

    if (tid < BM) Ptok[tid] = g_perm[row0 + tid];
    if (tid < BN) sbias[tid] = b1[(size_t)e*NI + n0 + tid];
    __syncthreads();

    float acc[2][8][4];
#pragma unroll
    for (int i=0;i<2;i++)
#pragma unroll
        for (int j=0;j<8;j++)
#pragma unroll
            for (int q=0;q<4;q++) acc[i][j][q]=0.f;

    float4 ra[4], rb[4];
    const int atok = Ptok[ar];
    auto pref = [&](int k0){
        if (atok >= 0){
            const float4* p = (const float4*)(x + (size_t)atok*NH + k0 + ah*16);
#pragma unroll
            for (int j=0;j<4;j++) ra[j] = p[j];
        } else {
#pragma unroll
            for (int j=0;j<4;j++) ra[j] = make_float4(0,0,0,0);
        }
        const float4* q = (const float4*)(W + (size_t)(k0+br)*NI + n0 + bq*16);
#pragma unroll
        for (int j=0;j<4;j++) rb[j] = q[j];
    };
    auto sts = [&](int b){
        float4* ad = (float4*)(As + b*A_STAGE + ar*A_LD + ah*16);
        float4* bd = (float4*)(Bs + b*B_STAGE + br*B_LD + bq*16);
#pragma unroll
        for (int j=0;j<4;j++){ ad[j] = cvt4(ra[j]); bd[j] = cvt4(rb[j]); }
    };

    const int KT = NH/BK;   // 24
    pref(0);
    for (int kt=0; kt<KT; kt++){
        int b = kt&1;
        sts(b);
        __syncthreads();
        if (kt+1<KT) pref((kt+1)*BK);
        compute_stage(As + b*A_STAGE, Bs + b*B_STAGE, wm, wn, gi, tg, acc);
        __syncthreads();
    }

    // epilogue: bias + gelu, direct to gmem
#pragma unroll
    for (int mt=0; mt<2; mt++){
#pragma unroll
        for (int half=0; half<2; half++){
            int gr = row0 + wm*32 + mt*16 + gi + half*8;
            float* orow = g_inter + (size_t)gr*NI + n0 + wn*64;
#pragma unroll
            for (int nt=0; nt<8; nt++){
                int c = nt*8 + tg*2;
                float v0 = acc[mt][nt][half*2]   + sbias[wn*64 + c];
                float v1 = acc[mt][nt][half*2+1] + sbias[wn*64 + c + 1];
                float2 o = make_float2(gelu_exact(v0), gelu_exact(v1));
                *(float2*)(orow + c) = o;
            }
        }
    }
}

// ========================= GEMM2 =========================
__global__ void __launch_bounds__(THREADS)
gemm2(const float* __restrict__ x, const float* __restrict__ w2,
      const float* __restrict__ b2)
{
    int tile = blockIdx.y;
    if (tile >= g_ntiles) return;
    const int e = g_tile_e[tile], row0 = g_tile_row0[tile];
    const int n0 = blockIdx.x * BN;
    const float* W = w2 + (size_t)e*NI*NH;

    extern __shared__ float sm[];
    float* As = sm;
    float* Bs = sm + 2*A_STAGE;
    __shared__ int Ptok[BM];
    __shared__ float sbias[BN];

    const int tid = threadIdx.x, w = tid>>5, l = tid&31;
    const int wm = w>>1, wn = w&1, gi = l>>2, tg = l&3;
    const int ar = tid>>1, ah = tid&1;
    const int br = tid>>3, bq = tid&7;

    if (tid < BM) Ptok[tid] = g_perm[row0 + tid];
    if (tid < BN) sbias[tid] = b2[(size_t)e*NH + n0 + tid];
    __syncthreads();

    float acc[2][8][4];
#pragma unroll
    for (int i=0;i<2;i++)
#pragma unroll
        for (int j=0;j<8;j++)
#pragma unroll
            for (int q=0;q<4;q++) acc[i][j][q]=0.f;

    float4 ra[4], rb[4];
    auto pref = [&](int k0){
        const float4* p = (const float4*)(g_inter + (size_t)(row0+ar)*NI + k0 + ah*16);
#pragma unroll
        for (int j=0;j<4;j++) ra[j] = p[j];
        const float4* q = (const float4*)(W + (size_t)(k0+br)*NH + n0 + bq*16);
#pragma unroll
        for (int j=0;j<4;j++) rb[j] = q[j];
    };
    auto sts = [&](int b){
        float4* ad = (float4*)(As + b*A_STAGE + ar*A_LD + ah*16);
        float4* bd = (float4*)(Bs + b*B_STAGE + br*B_LD + bq*16);
#pragma unroll
        for (int j=0;j<4;j++){ ad[j] = cvt4(ra[j]); bd[j] = cvt4(rb[j]); }
    };

    const int KT = NI/BK;   // 96
    pref(0);
    for (int kt=0; kt<KT; kt++){
        int b = kt&1;
        sts(b);
        __syncthreads();
        if (kt+1<KT) pref((kt+1)*BK);
        compute_stage(As + b*A_STAGE, Bs + b*B_STAGE, wm, wn, gi, tg, acc);
        __syncthreads();
    }

    // epilogue: +bias +residual, scatter to token order
#pragma unroll
    for (int mt=0; mt<2; mt++){
#pragma unroll
        for (int half=0; half<2; half++){
            int lr = wm*32 + mt*16 + gi + half*8;
            int tok = Ptok[lr];
            if (tok < 0) continue;
            float* orow = g_mid + (size_t)tok*NH + n0 + wn*64;
            const float* xr = x + (size_t)tok*NH + n0 + wn*64;
#pragma unroll
            for (int nt=0; nt<8; nt++){
                int c = nt*8 + tg*2;
                float2 r = *(const float2*)(xr + c);
                float2 o;
                o.x = acc[mt][nt][half*2]   + sbias[wn*64 + c]     + r.x;
                o.y = acc[mt][nt][half*2+1] + sbias[wn*64 + c + 1] + r.y;
                *(float2*)(orow + c) = o;
            }
        }
    }
}

// ========================= LayerNorm =========================
__global__ void ln_kernel(const float* __restrict__ gamma,
                          const float* __restrict__ beta,
                          float* __restrict__ out)
{
    const int t = blockIdx.x;
    const float* v = g_mid + (size_t)t*NH;
    float* o = out + (size_t)t*NH;
    float s=0.f, s2=0.f;
    for (int h=threadIdx.x; h<NH; h+=blockDim.x){ float a=v[h]; s+=a; s2+=a*a; }
#pragma unroll
    for (int off=16; off; off>>=1){
        s  += __shfl_down_sync(0xffffffffu, s, off);
        s2 += __shfl_down_sync(0xffffffffu, s2, off);
    }
    __shared__ float sh_s[8], sh_s2[8];
    int w = threadIdx.x>>5, l = threadIdx.x&31;
    if (l==0){ sh_s[w]=s; sh_s2[w]=s2; }
    __syncthreads();
    float S=0.f, S2=0.f;
#pragma unroll
    for (int i=0;i<8;i++){ S+=sh_s[i]; S2+=sh_s2[i]; }
    const float inv_h = 1.0f/(float)NH;
    float mean = S*inv_h;
    float var  = S2*inv_h - mean*mean;
    float rstd = rsqrtf(var + 1e-12f);
    for (int h=threadIdx.x; h<NH; h+=blockDim.x)
        o[h] = (v[h]-mean)*rstd*gamma[h] + beta[h];
}

extern "C" void kernel_launch(void* const* d_in, const int* in_sizes, int n_in,
                              void* d_out, int out_size)
{
    const float* x     = (const float*)d_in[0];
    const float* w1    = (const float*)d_in[1];
    const float* b1    = (const float*)d_in[2];
    const float* w2    = (const float*)d_in[3];
    const float* b2    = (const float*)d_in[4];
    const float* gamma = (const float*)d_in[5];
    const float* beta  = (const float*)d_in[6];
    const int*   eid   = (const int*)d_in[7];
    float* out = (float*)d_out;

    static bool attr_set = false;
    if (!attr_set){
        cudaFuncSetAttribute(gemm1, cudaFuncAttributeMaxDynamicSharedMemorySize, SMEM_BYTES);
        cudaFuncSetAttribute(gemm2, cudaFuncAttributeMaxDynamicSharedMemorySize, SMEM_BYTES);
        attr_set = true;
    }

    k_init<<<(NTP+255)/256, 256>>>();
    k_count<<<NT/256, 256>>>(eid);
    k_build<<<1,1>>>();
    k_scatter<<<NT/256, 256>>>(eid);

    gemm1<<<dim3(NI/BN, MAX_TILES), THREADS, SMEM_BYTES>>>(x, w1, b1);
    gemm2<<<dim3(NH/BN, MAX_TILES), THREADS, SMEM_BYTES>>>(x, w2, b2);
    ln_kernel<<<NT, 256>>>(gamma, beta, out);
}